// round 16
// baseline (speedup 1.0000x reference)
#include <cuda_runtime.h>
#include <cstdint>

#define NQ 4
#define NL 8

__device__ __align__(16) float g_T[112];   // 27 x (d0,d1,d2,pad)

__device__ __forceinline__ float2 cmul(float2 a, float2 b) {
    return make_float2(fmaf(a.x, b.x, -a.y * b.y), fmaf(a.x, b.y, a.y * b.x));
}
__device__ __forceinline__ float2 cfma(float2 a, float2 b, float2 acc) {
    acc.x = fmaf(a.x, b.x, fmaf(-a.y, b.y, acc.x));
    acc.y = fmaf(a.x, b.y, fmaf(a.y, b.x, acc.y));
    return acc;
}
__device__ __forceinline__ int cnot_map(int m, int c, int t) {
    int bc = 3 - c, bt = 3 - t;
    if ((m >> bc) & 1) m ^= (1 << bt);
    return m;
}

// One block, 256 threads. R15 setup (best measured): C built directly from
// gates, log-depth product tree, 2-stage Tucker, early PDL trigger.
__global__ void __launch_bounds__(256) vqc_setup(const float* __restrict__ w) {
    __shared__ float2 sGate[NL * NQ][4];
    __shared__ float2 sC[NL][256];
    __shared__ float2 sD[4][256];
    __shared__ float2 sE[2][256];
    __shared__ float2 sU[256];
    __shared__ float  sG[256];
    __shared__ float  sA[144];

    const int t = threadIdx.x;

    if (t < NL * NQ) {
        float phi = w[t * 3 + 0], th = w[t * 3 + 1], om = w[t * 3 + 2];
        float st, ct; __sincosf(0.5f * th, &st, &ct);
        float a = 0.5f * (phi + om), b = 0.5f * (phi - om);
        float sa, ca, sb, cb;
        __sincosf(a, &sa, &ca);
        __sincosf(b, &sb, &cb);
        sGate[t][0] = make_float2(ca * ct, -sa * ct);
        sGate[t][1] = make_float2(-cb * st, -sb * st);
        sGate[t][2] = make_float2(cb * st, -sb * st);
        sGate[t][3] = make_float2(ca * ct, sa * ct);
    }
    __syncthreads();

    // C_l[sigma(m)][n] = prod_w g_w[m_w][n_w]; sigma = CNOT ring.
    {
        int l = t >> 5, r = t & 31;
        const float2* g0 = sGate[l * 4 + 0];
        const float2* g1 = sGate[l * 4 + 1];
        const float2* g2 = sGate[l * 4 + 2];
        const float2* g3 = sGate[l * 4 + 3];
#pragma unroll
        for (int j = 0; j < 8; j++) {
            int idx = r + 32 * j;
            int m = idx >> 4, nn = idx & 15;
            int mp = m;
            mp = cnot_map(mp, 0, 1);
            mp = cnot_map(mp, 1, 2);
            mp = cnot_map(mp, 2, 3);
            mp = cnot_map(mp, 3, 0);
            float2 v01 = cmul(g0[((m >> 3) & 1) * 2 + ((nn >> 3) & 1)],
                              g1[((m >> 2) & 1) * 2 + ((nn >> 2) & 1)]);
            float2 v23 = cmul(g2[((m >> 1) & 1) * 2 + ((nn >> 1) & 1)],
                              g3[(m & 1) * 2 + (nn & 1)]);
            sC[l][mp * 16 + nn] = cmul(v01, v23);
        }
    }
    __syncthreads();

    // product tree: U = C7 C6 ... C0
    {
        int p = t >> 6, r = t & 63;
#pragma unroll
        for (int j = 0; j < 4; j++) {
            int idx = r + 64 * j;
            int i = idx >> 4, col = idx & 15;
            float2 acc = make_float2(0.0f, 0.0f);
#pragma unroll
            for (int k = 0; k < 16; k++)
                acc = cfma(sC[2 * p + 1][i * 16 + k], sC[2 * p][k * 16 + col], acc);
            sD[p][idx] = acc;
        }
    }
    __syncthreads();
    {
        int qq = t >> 7, r = t & 127;
#pragma unroll
        for (int j = 0; j < 2; j++) {
            int idx = r + 128 * j;
            int i = idx >> 4, col = idx & 15;
            float2 acc = make_float2(0.0f, 0.0f);
#pragma unroll
            for (int k = 0; k < 16; k++)
                acc = cfma(sD[2 * qq + 1][i * 16 + k], sD[2 * qq][k * 16 + col], acc);
            sE[qq][idx] = acc;
        }
    }
    __syncthreads();
    {
        int i = t >> 4, col = t & 15;
        float2 acc = make_float2(0.0f, 0.0f);
#pragma unroll
        for (int k = 0; k < 16; k++)
            acc = cfma(sE[1][i * 16 + k], sE[0][k * 16 + col], acc);
        sU[t] = acc;
    }
    __syncthreads();

    // H = U^dag Z0 U -> phase-folded real G
    {
        int j = t >> 4, k = t & 15;
        float hr = 0.0f, hi = 0.0f;
#pragma unroll
        for (int mm = 0; mm < 16; mm++) {
            float zz = ((mm >> 3) & 1) ? -1.0f : 1.0f;
            float2 uj = sU[mm * 16 + j], uk = sU[mm * 16 + k];
            hr += zz * (uj.x * uk.x + uj.y * uk.y);
            hi += zz * (uj.x * uk.y - uj.y * uk.x);
        }
        int q = (__popc(j) - __popc(k)) & 3;
        float gval = (q == 0) ? hr : (q == 1) ? -hi : (q == 2) ? -hr : hi;
        int gidx = 0;
#pragma unroll
        for (int wq = 0; wq < 4; wq++) {
            int bi = 3 - wq;
            int p = ((j >> bi) & 1) * 2 + ((k >> bi) & 1);
            gidx = gidx * 4 + p;
        }
        sG[gidx] = gval;
    }
    __syncthreads();

    const float V[4][3] = {{0.5f, 0.5f, 0.0f},
                           {0.0f, 0.0f, 0.5f},
                           {0.0f, 0.0f, 0.5f},
                           {0.5f, -0.5f, 0.0f}};
    if (t < 144) {  // Tucker stage A: (p2,p3) -> (c,d)
        int cd = t % 9, q01 = t / 9;
        int c = cd / 3, d = cd % 3;
        float acc = 0.0f;
#pragma unroll
        for (int p2 = 0; p2 < 4; p2++) {
#pragma unroll
            for (int p3 = 0; p3 < 4; p3++)
                acc += sG[q01 * 16 + p2 * 4 + p3] * (V[p2][c] * V[p3][d]);
        }
        sA[q01 * 9 + cd] = acc;
    }
    __syncthreads();
    if (t < 81) {  // Tucker stage B: (p0,p1) -> (a,b)
        int d = t % 3, c = (t / 3) % 3, b = (t / 9) % 3, a = t / 27;
        float acc = 0.0f;
#pragma unroll
        for (int p0 = 0; p0 < 4; p0++) {
#pragma unroll
            for (int p1 = 0; p1 < 4; p1++)
                acc += sA[(p0 * 4 + p1) * 9 + c * 3 + d] * (V[p0][a] * V[p1][b]);
        }
        g_T[(a * 9 + b * 3 + c) * 4 + d] = acc;
    } else if (t < 108) {
        g_T[(t - 81) * 4 + 3] = 0.0f;
    }

    __threadfence();
    __syncthreads();
    if (t == 0) cudaTriggerProgrammaticLaunchCompletion();
}

// ---- main building blocks ----
__device__ __forceinline__ void sincos4(const float4* v,
                                        float* c0, float* s0, float* c1, float* s1,
                                        float* c2, float* s2, float* c3, float* s3) {
#pragma unroll
    for (int k = 0; k < 4; k++) {
        __sincosf(v[k].x, &s0[k], &c0[k]);
        __sincosf(v[k].y, &s1[k], &c1[k]);
        __sincosf(v[k].z, &s2[k], &c2[k]);
        __sincosf(v[k].w, &s3[k], &c3[k]);
    }
}

// E-inline contraction for 4 strided samples (proven 64-reg form).
template <bool GUARD>
__device__ __forceinline__ void contract4(const float4* __restrict__ sT,
                                          float* __restrict__ out, int n, int i0,
                                          const float* c0, const float* s0,
                                          const float* c1, const float* s1,
                                          const float* c2, const float* s2,
                                          const float* c3, const float* s3) {
    float E[4];
#pragma unroll
    for (int u = 0; u < 9; u++) {
        const float4 t0 = sT[u * 3 + 0];
        const float4 t1 = sT[u * 3 + 1];
        const float4 t2 = sT[u * 3 + 2];
        const int a = u / 3, b = u % 3;  // compile-time under unroll
#pragma unroll
        for (int k = 0; k < 4; k++) {
            float a0 = fmaf(t0.z, s3[k], fmaf(t0.y, c3[k], t0.x));
            float a1 = fmaf(t1.z, s3[k], fmaf(t1.y, c3[k], t1.x));
            float a2 = fmaf(t2.z, s3[k], fmaf(t2.y, c3[k], t2.x));
            float r  = fmaf(a2, s2[k], fmaf(a1, c2[k], a0));
            if (a == 0 && b == 0) {
                E[k] = r;
            } else if (a == 0) {
                E[k] = fmaf(r, (b == 1) ? c1[k] : s1[k], E[k]);
            } else if (b == 0) {
                E[k] = fmaf(r, (a == 1) ? c0[k] : s0[k], E[k]);
            } else {
                float f0v = (a == 1) ? c0[k] : s0[k];
                float f1v = (b == 1) ? c1[k] : s1[k];
                E[k] = fmaf(r * f0v, f1v, E[k]);
            }
        }
    }
#pragma unroll
    for (int k = 0; k < 4; k++) {
        int i = i0 + 32 * k;
        if (!GUARD || i < n) out[i] = E[k];
    }
}

// Main: each warp owns TWO consecutive 128-sample tiles; ALL 8 LDG.128 issue
// in the prologue (R13's fatal mid-kernel load chain fixed). Tile B's x
// values parked in thread-private shared slots (no sync needed: each thread
// reads only what it wrote; [k][tid] layout is conflict-free). 512 blocks at
// 4 CTA/SM -> single resident wave, no drain rounds.
__global__ void __launch_bounds__(256, 4) vqc_main(const float4* __restrict__ x,
                                                   float* __restrict__ out, int n) {
    __shared__ __align__(16) float4 sT[28];
    __shared__ __align__(16) float4 sXB[4][256];   // tile B x, thread-private slots
    const int t = threadIdx.x;
    const int warp = t >> 5, lane = t & 31;
    const int regionBase = (blockIdx.x * 8 + warp) * 256;  // 2 tiles per warp
    const int iA = regionBase + lane;
    const int iB = regionBase + 128 + lane;
    const bool anyA = (regionBase < n);
    const bool anyB = (regionBase + 128 < n);
    const bool fullRegion = (regionBase + 255 < n);

    // ---- prologue: ALL loads in flight, then trig A (overlaps setup/PDL) ----
    float4 vA[4];
#pragma unroll
    for (int k = 0; k < 4; k++) {
        int ia = iA + 32 * k;
        int ib = iB + 32 * k;
        vA[k] = (anyA && (fullRegion || ia < n)) ? x[ia] : make_float4(0.f, 0.f, 0.f, 0.f);
        float4 vb = (fullRegion || (anyB && ib < n)) ? x[ib] : make_float4(0.f, 0.f, 0.f, 0.f);
        sXB[k][t] = vb;   // park tile B; read back by the same thread later
    }

    float c0[4], s0[4], c1[4], s1[4], c2[4], s2[4], c3[4], s3[4];
    sincos4(vA, c0, s0, c1, s1, c2, s2, c3, s3);

    // ---- wait for setup's early trigger, stage T ----
    cudaGridDependencySynchronize();
    if (t < 28) sT[t] = reinterpret_cast<const float4*>(g_T)[t];
    __syncthreads();

    if (!anyA) return;

    if (fullRegion) {
        contract4<false>(sT, out, n, iA, c0, s0, c1, s1, c2, s2, c3, s3);
        float4 vB[4];
#pragma unroll
        for (int k = 0; k < 4; k++) vB[k] = sXB[k][t];
        sincos4(vB, c0, s0, c1, s1, c2, s2, c3, s3);
        contract4<false>(sT, out, n, iB, c0, s0, c1, s1, c2, s2, c3, s3);
    } else {
        contract4<true>(sT, out, n, iA, c0, s0, c1, s1, c2, s2, c3, s3);
        if (anyB) {
            float4 vB[4];
#pragma unroll
            for (int k = 0; k < 4; k++) vB[k] = sXB[k][t];
            sincos4(vB, c0, s0, c1, s1, c2, s2, c3, s3);
            contract4<true>(sT, out, n, iB, c0, s0, c1, s1, c2, s2, c3, s3);
        }
    }
}

extern "C" void kernel_launch(void* const* d_in, const int* in_sizes, int n_in,
                              void* d_out, int out_size) {
    const float* x = (const float*)d_in[0];        // (B, 4)
    const float* w = (const float*)d_in[1];        // (8, 4, 3)
    float* out = (float*)d_out;                    // (B,)
    int n = out_size;                              // B

    vqc_setup<<<1, 256>>>(w);

    int blocks = (n + 2047) / 2048;                // 2048 samples per block

    cudaLaunchConfig_t cfg = {};
    cfg.gridDim = dim3((unsigned)blocks, 1, 1);
    cfg.blockDim = dim3(256, 1, 1);
    cfg.dynamicSmemBytes = 0;
    cfg.stream = 0;
    cudaLaunchAttribute attrs[1];
    attrs[0].id = cudaLaunchAttributeProgrammaticStreamSerialization;
    attrs[0].val.programmaticStreamSerializationAllowed = 1;
    cfg.attrs = attrs;
    cfg.numAttrs = 1;
    cudaLaunchKernelEx(&cfg, vqc_main, (const float4*)x, out, n);
}

// round 17
// speedup vs baseline: 1.8319x; 1.8319x over previous
#include <cuda_runtime.h>
#include <cstdint>

#define NQ 4
#define NL 8

typedef unsigned long long u64;

__device__ __align__(16) float g_T[112];   // 27 x (d0,d1,d2,pad)

__device__ __forceinline__ float2 cmul(float2 a, float2 b) {
    return make_float2(fmaf(a.x, b.x, -a.y * b.y), fmaf(a.x, b.y, a.y * b.x));
}
__device__ __forceinline__ float2 cfma(float2 a, float2 b, float2 acc) {
    acc.x = fmaf(a.x, b.x, fmaf(-a.y, b.y, acc.x));
    acc.y = fmaf(a.x, b.y, fmaf(a.y, b.x, acc.y));
    return acc;
}
__device__ __forceinline__ int cnot_map(int m, int c, int t) {
    int bc = 3 - c, bt = 3 - t;
    if ((m >> bc) & 1) m ^= (1 << bt);
    return m;
}

// packed f32x2 helpers (ptxas never auto-fuses; must be PTX)
__device__ __forceinline__ u64 pk(float lo, float hi) {
    u64 r; asm("mov.b64 %0, {%1,%2};" : "=l"(r) : "f"(lo), "f"(hi)); return r;
}
__device__ __forceinline__ u64 dup2(float v) { return pk(v, v); }
__device__ __forceinline__ void upk(u64 v, float& lo, float& hi) {
    asm("mov.b64 {%0,%1}, %2;" : "=f"(lo), "=f"(hi) : "l"(v));
}
__device__ __forceinline__ u64 fma2(u64 a, u64 b, u64 c) {
    u64 d; asm("fma.rn.f32x2 %0, %1, %2, %3;" : "=l"(d) : "l"(a), "l"(b), "l"(c)); return d;
}

// One block, 256 threads. R15 setup (best measured), verbatim.
__global__ void __launch_bounds__(256) vqc_setup(const float* __restrict__ w) {
    __shared__ float2 sGate[NL * NQ][4];
    __shared__ float2 sC[NL][256];
    __shared__ float2 sD[4][256];
    __shared__ float2 sE[2][256];
    __shared__ float2 sU[256];
    __shared__ float  sG[256];
    __shared__ float  sA[144];

    const int t = threadIdx.x;

    if (t < NL * NQ) {
        float phi = w[t * 3 + 0], th = w[t * 3 + 1], om = w[t * 3 + 2];
        float st, ct; __sincosf(0.5f * th, &st, &ct);
        float a = 0.5f * (phi + om), b = 0.5f * (phi - om);
        float sa, ca, sb, cb;
        __sincosf(a, &sa, &ca);
        __sincosf(b, &sb, &cb);
        sGate[t][0] = make_float2(ca * ct, -sa * ct);
        sGate[t][1] = make_float2(-cb * st, -sb * st);
        sGate[t][2] = make_float2(cb * st, -sb * st);
        sGate[t][3] = make_float2(ca * ct, sa * ct);
    }
    __syncthreads();

    {
        int l = t >> 5, r = t & 31;
        const float2* g0 = sGate[l * 4 + 0];
        const float2* g1 = sGate[l * 4 + 1];
        const float2* g2 = sGate[l * 4 + 2];
        const float2* g3 = sGate[l * 4 + 3];
#pragma unroll
        for (int j = 0; j < 8; j++) {
            int idx = r + 32 * j;
            int m = idx >> 4, nn = idx & 15;
            int mp = m;
            mp = cnot_map(mp, 0, 1);
            mp = cnot_map(mp, 1, 2);
            mp = cnot_map(mp, 2, 3);
            mp = cnot_map(mp, 3, 0);
            float2 v01 = cmul(g0[((m >> 3) & 1) * 2 + ((nn >> 3) & 1)],
                              g1[((m >> 2) & 1) * 2 + ((nn >> 2) & 1)]);
            float2 v23 = cmul(g2[((m >> 1) & 1) * 2 + ((nn >> 1) & 1)],
                              g3[(m & 1) * 2 + (nn & 1)]);
            sC[l][mp * 16 + nn] = cmul(v01, v23);
        }
    }
    __syncthreads();

    {
        int p = t >> 6, r = t & 63;
#pragma unroll
        for (int j = 0; j < 4; j++) {
            int idx = r + 64 * j;
            int i = idx >> 4, col = idx & 15;
            float2 acc = make_float2(0.0f, 0.0f);
#pragma unroll
            for (int k = 0; k < 16; k++)
                acc = cfma(sC[2 * p + 1][i * 16 + k], sC[2 * p][k * 16 + col], acc);
            sD[p][idx] = acc;
        }
    }
    __syncthreads();
    {
        int qq = t >> 7, r = t & 127;
#pragma unroll
        for (int j = 0; j < 2; j++) {
            int idx = r + 128 * j;
            int i = idx >> 4, col = idx & 15;
            float2 acc = make_float2(0.0f, 0.0f);
#pragma unroll
            for (int k = 0; k < 16; k++)
                acc = cfma(sD[2 * qq + 1][i * 16 + k], sD[2 * qq][k * 16 + col], acc);
            sE[qq][idx] = acc;
        }
    }
    __syncthreads();
    {
        int i = t >> 4, col = t & 15;
        float2 acc = make_float2(0.0f, 0.0f);
#pragma unroll
        for (int k = 0; k < 16; k++)
            acc = cfma(sE[1][i * 16 + k], sE[0][k * 16 + col], acc);
        sU[t] = acc;
    }
    __syncthreads();

    {
        int j = t >> 4, k = t & 15;
        float hr = 0.0f, hi = 0.0f;
#pragma unroll
        for (int mm = 0; mm < 16; mm++) {
            float zz = ((mm >> 3) & 1) ? -1.0f : 1.0f;
            float2 uj = sU[mm * 16 + j], uk = sU[mm * 16 + k];
            hr += zz * (uj.x * uk.x + uj.y * uk.y);
            hi += zz * (uj.x * uk.y - uj.y * uk.x);
        }
        int q = (__popc(j) - __popc(k)) & 3;
        float gval = (q == 0) ? hr : (q == 1) ? -hi : (q == 2) ? -hr : hi;
        int gidx = 0;
#pragma unroll
        for (int wq = 0; wq < 4; wq++) {
            int bi = 3 - wq;
            int p = ((j >> bi) & 1) * 2 + ((k >> bi) & 1);
            gidx = gidx * 4 + p;
        }
        sG[gidx] = gval;
    }
    __syncthreads();

    const float V[4][3] = {{0.5f, 0.5f, 0.0f},
                           {0.0f, 0.0f, 0.5f},
                           {0.0f, 0.0f, 0.5f},
                           {0.5f, -0.5f, 0.0f}};
    if (t < 144) {  // Tucker stage A: (p2,p3) -> (c,d)
        int cd = t % 9, q01 = t / 9;
        int c = cd / 3, d = cd % 3;
        float acc = 0.0f;
#pragma unroll
        for (int p2 = 0; p2 < 4; p2++) {
#pragma unroll
            for (int p3 = 0; p3 < 4; p3++)
                acc += sG[q01 * 16 + p2 * 4 + p3] * (V[p2][c] * V[p3][d]);
        }
        sA[q01 * 9 + cd] = acc;
    }
    __syncthreads();
    if (t < 81) {  // Tucker stage B: (p0,p1) -> (a,b)
        int d = t % 3, c = (t / 3) % 3, b = (t / 9) % 3, a = t / 27;
        float acc = 0.0f;
#pragma unroll
        for (int p0 = 0; p0 < 4; p0++) {
#pragma unroll
            for (int p1 = 0; p1 < 4; p1++)
                acc += sA[(p0 * 4 + p1) * 9 + c * 3 + d] * (V[p0][a] * V[p1][b]);
        }
        g_T[(a * 9 + b * 3 + c) * 4 + d] = acc;
    } else if (t < 108) {
        g_T[(t - 81) * 4 + 3] = 0.0f;
    }

    __threadfence();
    __syncthreads();
    if (t == 0) cudaTriggerProgrammaticLaunchCompletion();
}

// Packed-pair contraction: 4 samples as 2 f32x2 pairs (samples 2p, 2p+1 of
// the k-order, i.e. gmem indices i0+64p and i0+64p+32). T lanes duplicated
// in REGISTERS (not shared — R4's defect); r9-form independent chains kept.
template <bool GUARD>
__device__ __forceinline__ void run_tile_packed(
    float* __restrict__ out, int n, const float4* __restrict__ sT, int i0,
    const u64* c0p, const u64* s0p, const u64* c1p, const u64* s1p,
    const u64* c2p, const u64* s2p, const u64* c3p, const u64* s3p) {
    u64 r9[2][9];
#pragma unroll
    for (int u = 0; u < 9; u++) {
        const float4 t0 = sT[u * 3 + 0];
        const float4 t1 = sT[u * 3 + 1];
        const float4 t2 = sT[u * 3 + 2];
        u64 T0x = dup2(t0.x), T0y = dup2(t0.y), T0z = dup2(t0.z);
        u64 T1x = dup2(t1.x), T1y = dup2(t1.y), T1z = dup2(t1.z);
        u64 T2x = dup2(t2.x), T2y = dup2(t2.y), T2z = dup2(t2.z);
#pragma unroll
        for (int p = 0; p < 2; p++) {
            u64 a0 = fma2(T0z, s3p[p], fma2(T0y, c3p[p], T0x));
            u64 a1 = fma2(T1z, s3p[p], fma2(T1y, c3p[p], T1x));
            u64 a2 = fma2(T2z, s3p[p], fma2(T2y, c3p[p], T2x));
            r9[p][u] = fma2(a2, s2p[p], fma2(a1, c2p[p], a0));
        }
    }
#pragma unroll
    for (int p = 0; p < 2; p++) {
        u64 b0 = fma2(r9[p][2], s1p[p], fma2(r9[p][1], c1p[p], r9[p][0]));
        u64 b1 = fma2(r9[p][5], s1p[p], fma2(r9[p][4], c1p[p], r9[p][3]));
        u64 b2 = fma2(r9[p][8], s1p[p], fma2(r9[p][7], c1p[p], r9[p][6]));
        u64 E  = fma2(b2, s0p[p], fma2(b1, c0p[p], b0));
        float e0, e1; upk(E, e0, e1);
        int ia = i0 + 64 * p;        // sample k = 2p
        int ib = i0 + 64 * p + 32;   // sample k = 2p+1
        if (!GUARD || ia < n) out[ia] = e0;
        if (!GUARD || ib < n) out[ib] = e1;
    }
}

// Main (R15 structure): warp owns one 128-sample tile, all loads + sincos in
// the prologue before the PDL sync, exact 1024-block grid.
__global__ void __launch_bounds__(256) vqc_main(const float4* __restrict__ x,
                                                float* __restrict__ out, int n) {
    __shared__ __align__(16) float4 sT[28];
    const int t = threadIdx.x;
    const int warp = t >> 5, lane = t & 31;
    const int tileBase = (blockIdx.x * 8 + warp) * 128;
    const int i0 = tileBase + lane;
    const bool active = (tileBase < n);
    const bool fullTile = (tileBase + 127 < n);

    // ---- T-independent prologue (overlaps setup via PDL) ----
    float c0[4], s0[4], c1[4], s1[4], c2[4], s2[4], c3[4], s3[4];
#pragma unroll
    for (int k = 0; k < 4; k++) {
        int i = i0 + 32 * k;
        float4 v = (active && (fullTile || i < n)) ? x[i]
                                                   : make_float4(0.f, 0.f, 0.f, 0.f);
        __sincosf(v.x, &s0[k], &c0[k]);
        __sincosf(v.y, &s1[k], &c1[k]);
        __sincosf(v.z, &s2[k], &c2[k]);
        __sincosf(v.w, &s3[k], &c3[k]);
    }
    // pack sample pairs (2p, 2p+1) into f32x2 lanes
    u64 c0p[2], s0p[2], c1p[2], s1p[2], c2p[2], s2p[2], c3p[2], s3p[2];
#pragma unroll
    for (int p = 0; p < 2; p++) {
        c0p[p] = pk(c0[2 * p], c0[2 * p + 1]);
        s0p[p] = pk(s0[2 * p], s0[2 * p + 1]);
        c1p[p] = pk(c1[2 * p], c1[2 * p + 1]);
        s1p[p] = pk(s1[2 * p], s1[2 * p + 1]);
        c2p[p] = pk(c2[2 * p], c2[2 * p + 1]);
        s2p[p] = pk(s2[2 * p], s2[2 * p + 1]);
        c3p[p] = pk(c3[2 * p], c3[2 * p + 1]);
        s3p[p] = pk(s3[2 * p], s3[2 * p + 1]);
    }

    // ---- wait for setup's early trigger, stage T ----
    cudaGridDependencySynchronize();
    if (t < 28) sT[t] = reinterpret_cast<const float4*>(g_T)[t];
    __syncthreads();

    if (!active) return;
    if (fullTile) {
        run_tile_packed<false>(out, n, sT, i0, c0p, s0p, c1p, s1p, c2p, s2p, c3p, s3p);
    } else {
        run_tile_packed<true>(out, n, sT, i0, c0p, s0p, c1p, s1p, c2p, s2p, c3p, s3p);
    }
}

extern "C" void kernel_launch(void* const* d_in, const int* in_sizes, int n_in,
                              void* d_out, int out_size) {
    const float* x = (const float*)d_in[0];        // (B, 4)
    const float* w = (const float*)d_in[1];        // (8, 4, 3)
    float* out = (float*)d_out;                    // (B,)
    int n = out_size;                              // B

    vqc_setup<<<1, 256>>>(w);

    int ntiles = (n + 127) / 128;
    int blocks = (ntiles + 7) / 8;                 // one tile per warp, exact

    cudaLaunchConfig_t cfg = {};
    cfg.gridDim = dim3((unsigned)blocks, 1, 1);
    cfg.blockDim = dim3(256, 1, 1);
    cfg.dynamicSmemBytes = 0;
    cfg.stream = 0;
    cudaLaunchAttribute attrs[1];
    attrs[0].id = cudaLaunchAttributeProgrammaticStreamSerialization;
    attrs[0].val.programmaticStreamSerializationAllowed = 1;
    cfg.attrs = attrs;
    cfg.numAttrs = 1;
    cudaLaunchKernelEx(&cfg, vqc_main, (const float4*)x, out, n);
}